// round 1
// baseline (speedup 1.0000x reference)
#include <cuda_runtime.h>
#include <math.h>

#define NB 8
#define NT 16384
#define NQ 256
#define NR 64
#define ND 64
#define NS 256
#define NL 20
#define OUTW 14337
#define OUTW_PAD 14368
#define TT 128

// Scratch (device globals; no allocation allowed)
__device__ float g_h0[NB * NR * NT];
__device__ float g_h1[NB * NR * NT];
__device__ float g_total[NB * NS * OUTW_PAD];
__device__ float g_c1[NB * NS * OUTW_PAD];
__device__ float g_w1T[NS * NS];
__device__ float g_w2T[NQ * NS];

__global__ void zero_kernel(float* __restrict__ p, int n) {
    int i = blockIdx.x * blockDim.x + threadIdx.x;
    if (i < n) p[i] = 0.f;
}

// wT[k][s] = w[s][k], 256x256
__global__ void transpose_kernel(const float* __restrict__ w, float* __restrict__ wT) {
    int i = blockIdx.x * 256 + threadIdx.x;
    int k = i >> 8, s = i & 255;
    wT[i] = w[(s << 8) + k];
}

// h[b][r][t] = cw[r][x[b,t]][0] + cw[r][x[b,t+1]][1] + cb[r]   (one-hot conv == gather)
__global__ void __launch_bounds__(256) causal_kernel(
    const int* __restrict__ x, const float* __restrict__ cw,
    const float* __restrict__ cb, float* __restrict__ h)
{
    extern __shared__ float sm[];               // 32768 floats: cw [r][q][k]
    __shared__ float cbS[64];
    for (int i = threadIdx.x; i < NR * NQ * 2; i += 256) sm[i] = cw[i];
    if (threadIdx.x < 64) cbS[threadIdx.x] = cb[threadIdx.x];
    __syncthreads();
    int b = blockIdx.y;
    int t = blockIdx.x * 256 + threadIdx.x;
    if (t >= NT - 1) return;
    int q0 = x[b * NT + t] * 2;
    int q1 = x[b * NT + t + 1] * 2 + 1;
    float* hp = h + ((size_t)b << 20) + t;
    #pragma unroll 4
    for (int r = 0; r < 64; r++) {
        hp[r << 14] = sm[(r << 9) + q0] + sm[(r << 9) + q1] + cbS[r];
    }
}

// Fused WaveNet layer: f/g dilated conv -> tanh*sigmoid -> dense residual + skip accum.
__global__ void __launch_bounds__(256) layer_kernel(
    const float* __restrict__ hcur, float* __restrict__ hnext,
    const float* __restrict__ fw, const float* __restrict__ fb,
    const float* __restrict__ gw, const float* __restrict__ gb,
    const float* __restrict__ dw, const float* __restrict__ db,
    const float* __restrict__ sw, const float* __restrict__ sb,
    float* __restrict__ total,
    int dil, int Lh, int Ti, int off)
{
    extern __shared__ float smem[];
    float* wfT = smem;              // [2][64][64]  (k,r,dc)   8192
    float* wgT = wfT + 8192;        // 8192
    float* dwS = wgT + 8192;        // [r][dc]                 4096
    float* swS = dwS + 4096;        // [s][dc]                16384
    float* hA  = swS + 16384;       // 8256 (h tap0 tile; reused as outS[64][129])
    float* hB  = hA + 8256;         // [64][128] h tap1 tile   8192
                                    // total 53312 floats = 213248 B

    const int tid = threadIdx.x;
    const int b = blockIdx.y;
    const int t0 = blockIdx.x * TT;

    // stage weights; fw/gw transposed to (k,r,dc) so inner reads are conflict-free
    #pragma unroll 1
    for (int i = tid; i < 8192; i += 256) {
        int dc = i >> 7, r = (i >> 1) & 63, k = i & 1;
        int si = (k << 12) + (r << 6) + dc;
        wfT[si] = fw[i];
        wgT[si] = gw[i];
    }
    for (int i = tid; i < 4096; i += 256) dwS[i] = dw[i];
    for (int i = tid; i < 16384; i += 256) swS[i] = sw[i];

    const float* hbase = hcur + ((size_t)b << 20);
    #pragma unroll 1
    for (int i = tid; i < 64 * TT; i += 256) {
        int r = i >> 7, tt = i & 127;
        int ta = t0 + tt;
        hA[i] = (ta < Lh) ? hbase[(r << 14) + ta] : 0.f;
        int tb = ta + dil;
        hB[i] = (tb < Lh) ? hbase[(r << 14) + tb] : 0.f;
    }
    __syncthreads();

    // ---- Phase 1: filter/gate GEMM (K=64, 2 taps) + activation -> outS ----
    {
        const int dc = tid & 63;
        const int tg = tid >> 6;    // 0..3 : 32 time cols each
        float facc[32], gacc[32];
        float fbv = fb[dc], gbv = gb[dc];
        #pragma unroll
        for (int j = 0; j < 32; j++) { facc[j] = fbv; gacc[j] = gbv; }
        const float* hap = hA + tg * 32;
        const float* hbp = hB + tg * 32;
        #pragma unroll 2
        for (int r = 0; r < 64; r++) {
            float wf0 = wfT[(r << 6) + dc];
            float wf1 = wfT[4096 + (r << 6) + dc];
            float wg0 = wgT[(r << 6) + dc];
            float wg1 = wgT[4096 + (r << 6) + dc];
            const float* ha = hap + (r << 7);
            const float* hb = hbp + (r << 7);
            #pragma unroll
            for (int j = 0; j < 32; j++) {
                float a = ha[j];
                float c = hb[j];
                facc[j] += wf0 * a;
                facc[j] += wf1 * c;
                gacc[j] += wg0 * a;
                gacc[j] += wg1 * c;
            }
        }
        // out = tanh(f) * sigmoid(g), via exp (clamped to avoid inf/NaN)
        #pragma unroll
        for (int j = 0; j < 32; j++) {
            float ef = __expf(fminf(-2.f * facc[j], 80.f));
            float th = __fdividef(1.f - ef, 1.f + ef);
            float eg = __expf(fminf(-gacc[j], 80.f));
            facc[j] = th * __fdividef(1.f, 1.f + eg);
        }
        __syncthreads();                 // all hA reads done -> safe to overwrite
        float* row = hA + dc * 129 + tg * 32;   // padded row: conflict-free
        #pragma unroll
        for (int j = 0; j < 32; j++) row[j] = facc[j];
    }
    __syncthreads();

    const float* outS = hA;
    const int tl = tid & 31;
    const int wp = tid >> 5;   // 0..7

    // ---- Phase 2: dense 1x1 (D->R) + residual -> hnext ----
    {
        float acc[8][4];
        #pragma unroll
        for (int m = 0; m < 8; m++) {
            float dbv = db[wp + (m << 3)];
            #pragma unroll
            for (int q = 0; q < 4; q++) acc[m][q] = dbv;
        }
        #pragma unroll 1
        for (int dcc = 0; dcc < 64; dcc++) {
            float o0 = outS[dcc * 129 + tl];
            float o1 = outS[dcc * 129 + tl + 32];
            float o2 = outS[dcc * 129 + tl + 64];
            float o3 = outS[dcc * 129 + tl + 96];
            #pragma unroll
            for (int m = 0; m < 8; m++) {
                float w = dwS[((wp + (m << 3)) << 6) + dcc];
                acc[m][0] += w * o0;
                acc[m][1] += w * o1;
                acc[m][2] += w * o2;
                acc[m][3] += w * o3;
            }
        }
        float* hnb = hnext + ((size_t)b << 20);
        #pragma unroll
        for (int m = 0; m < 8; m++) {
            int r = wp + (m << 3);
            #pragma unroll
            for (int q = 0; q < 4; q++) {
                int tt = tl + (q << 5);
                int tgl = t0 + tt;
                if (tgl < Ti) hnb[(r << 14) + tgl] = hB[(r << 7) + tt] + acc[m][q];
            }
        }
    }

    // ---- Phase 3: skip 1x1 (D->S), RMW into total (lane-contiguous in time) ----
    #pragma unroll 1
    for (int half = 0; half < 2; half++) {
        float acc[16][4];
        #pragma unroll
        for (int m = 0; m < 16; m++)
            #pragma unroll
            for (int q = 0; q < 4; q++) acc[m][q] = 0.f;
        #pragma unroll 1
        for (int dcc = 0; dcc < 64; dcc++) {
            float o0 = outS[dcc * 129 + tl];
            float o1 = outS[dcc * 129 + tl + 32];
            float o2 = outS[dcc * 129 + tl + 64];
            float o3 = outS[dcc * 129 + tl + 96];
            #pragma unroll
            for (int m = 0; m < 16; m++) {
                int s = wp + (half << 7) + (m << 3);
                float w = swS[(s << 6) + dcc];
                acc[m][0] += w * o0;
                acc[m][1] += w * o1;
                acc[m][2] += w * o2;
                acc[m][3] += w * o3;
            }
        }
        #pragma unroll
        for (int m = 0; m < 16; m++) {
            int s = wp + (half << 7) + (m << 3);
            float sbv = sb[s];
            float* tb2 = total + (size_t)((b << 8) + s) * OUTW_PAD - off;
            #pragma unroll
            for (int q = 0; q < 4; q++) {
                int tgl = t0 + tl + (q << 5);
                if (tgl >= off && tgl < Ti) tb2[tgl] += acc[m][q] + sbv;
            }
        }
    }
}

// out[b][s][t] = bias[s] + sum_k wT[k][s] * relu(in[b][k][t])     (256x256 GEMM)
__global__ void __launch_bounds__(256) post_kernel(
    const float* __restrict__ in, const float* __restrict__ wT,
    const float* __restrict__ bias, float* __restrict__ outp, int ostride)
{
    extern __shared__ float smem[];
    float* inS = smem;            // [256][64]
    float* wS  = smem + 16384;    // [64][256] staged per k-chunk
    const int tid = threadIdx.x;
    const int b = blockIdx.y;
    const int t0 = blockIdx.x << 6;

    #pragma unroll 1
    for (int i = tid; i < 16384; i += 256) {
        int k = i >> 6, tt = i & 63;
        int t = t0 + tt;
        float v = (t < OUTW) ? in[(size_t)((b << 8) + k) * OUTW_PAD + t] : 0.f;
        inS[i] = fmaxf(v, 0.f);
    }
    const int tl = tid & 31;
    const int wp = tid >> 5;
    float acc[32][2];
    #pragma unroll
    for (int m = 0; m < 32; m++) {
        float bv = bias[wp + (m << 3)];
        acc[m][0] = bv; acc[m][1] = bv;
    }
    #pragma unroll 1
    for (int kc = 0; kc < 4; kc++) {
        __syncthreads();
        #pragma unroll 1
        for (int i = tid; i < 16384; i += 256) wS[i] = wT[(kc << 14) + i];
        __syncthreads();
        #pragma unroll 1
        for (int kk = 0; kk < 64; kk++) {
            float v0 = inS[(((kc << 6) + kk) << 6) + tl];
            float v1 = inS[(((kc << 6) + kk) << 6) + tl + 32];
            #pragma unroll
            for (int m = 0; m < 32; m++) {
                float w = wS[(kk << 8) + wp + (m << 3)];
                acc[m][0] += w * v0;
                acc[m][1] += w * v1;
            }
        }
    }
    #pragma unroll
    for (int m = 0; m < 32; m++) {
        int s = wp + (m << 3);
        float* op = outp + (size_t)((b << 8) + s) * ostride + t0;
        if (t0 + tl < OUTW) op[tl] = acc[m][0];
        if (t0 + tl + 32 < OUTW) op[tl + 32] = acc[m][1];
    }
}

extern "C" void kernel_launch(void* const* d_in, const int* in_sizes, int n_in,
                              void* d_out, int out_size)
{
    const int*   x        = (const int*)d_in[0];
    const float* causal_w = (const float*)d_in[1];
    const float* causal_b = (const float*)d_in[2];
    const float* filt_w   = (const float*)d_in[3];
    const float* filt_b   = (const float*)d_in[4];
    const float* gate_w   = (const float*)d_in[5];
    const float* gate_b   = (const float*)d_in[6];
    const float* dense_w  = (const float*)d_in[7];
    const float* dense_b  = (const float*)d_in[8];
    const float* skip_w   = (const float*)d_in[9];
    const float* skip_b   = (const float*)d_in[10];
    const float* pp1_w    = (const float*)d_in[11];
    const float* pp1_b    = (const float*)d_in[12];
    const float* pp2_w    = (const float*)d_in[13];
    const float* pp2_b    = (const float*)d_in[14];
    float* out = (float*)d_out;

    float *h0, *h1, *total, *c1, *w1T, *w2T;
    cudaGetSymbolAddress((void**)&h0, g_h0);
    cudaGetSymbolAddress((void**)&h1, g_h1);
    cudaGetSymbolAddress((void**)&total, g_total);
    cudaGetSymbolAddress((void**)&c1, g_c1);
    cudaGetSymbolAddress((void**)&w1T, g_w1T);
    cudaGetSymbolAddress((void**)&w2T, g_w2T);

    static const int dil[NL] = {1, 2, 4, 8, 16, 32, 64, 128, 256, 512,
                                1, 2, 4, 8, 16, 32, 64, 128, 256, 512};

    cudaFuncSetAttribute(layer_kernel,  cudaFuncAttributeMaxDynamicSharedMemorySize, 53312 * 4);
    cudaFuncSetAttribute(causal_kernel, cudaFuncAttributeMaxDynamicSharedMemorySize, 32768 * 4);
    cudaFuncSetAttribute(post_kernel,   cudaFuncAttributeMaxDynamicSharedMemorySize, 32768 * 4);

    int nTot = NB * NS * OUTW_PAD;
    zero_kernel<<<(nTot + 255) / 256, 256>>>(total, nTot);

    dim3 cg((NT - 1 + 255) / 256, NB);
    causal_kernel<<<cg, 256, 32768 * 4>>>(x, causal_w, causal_b, h0);

    float* hc = h0;
    float* hn = h1;
    int Lh = NT - 1;
    for (int i = 0; i < NL; i++) {
        int d = dil[i];
        int Ti = Lh - d;
        int off = Ti - OUTW;
        dim3 g((Ti + TT - 1) / TT, NB);
        layer_kernel<<<g, 256, 53312 * 4>>>(
            hc, hn,
            filt_w + (size_t)i * ND * NR * 2, filt_b + (size_t)i * ND,
            gate_w + (size_t)i * ND * NR * 2, gate_b + (size_t)i * ND,
            dense_w + (size_t)i * NR * ND,    dense_b + (size_t)i * NR,
            skip_w + (size_t)i * NS * ND,     skip_b + (size_t)i * NS,
            total, d, Lh, Ti, off);
        float* tmp = hc; hc = hn; hn = tmp;
        Lh = Ti;
    }

    transpose_kernel<<<256, 256>>>(pp1_w, w1T);
    transpose_kernel<<<256, 256>>>(pp2_w, w2T);

    dim3 pg((OUTW + 63) / 64, NB);
    post_kernel<<<pg, 256, 32768 * 4>>>(total, w1T, pp1_b, c1, OUTW_PAD);
    post_kernel<<<pg, 256, 32768 * 4>>>(c1, w2T, pp2_b, out, OUTW);
}

// round 2
// speedup vs baseline: 1.7633x; 1.7633x over previous
#include <cuda_runtime.h>
#include <math.h>

#define NB 8
#define NT 16384
#define NQ 256
#define NR 64
#define ND 64
#define NS 256
#define NL 20
#define OUTW 14337
#define OUTW_PAD 14368
#define TT 256

// Scratch (device globals; no allocation allowed)
__device__ float g_h0[NB * NR * NT];
__device__ float g_h1[NB * NR * NT];
__device__ float g_total[NB * NS * OUTW_PAD];
__device__ float g_c1[NB * NS * OUTW_PAD];
__device__ float g_w1T[NS * NS];
__device__ float g_w2T[NQ * NS];

__global__ void zero_kernel(float* __restrict__ p, int n) {
    int i = blockIdx.x * blockDim.x + threadIdx.x;
    if (i < n) p[i] = 0.f;
}

// wT[k][s] = w[s][k], 256x256
__global__ void transpose_kernel(const float* __restrict__ w, float* __restrict__ wT) {
    int i = blockIdx.x * 256 + threadIdx.x;
    int k = i >> 8, s = i & 255;
    wT[i] = w[(s << 8) + k];
}

// h[b][r][t] = cw[r][x[b,t]][0] + cw[r][x[b,t+1]][1] + cb[r]   (one-hot conv == gather)
__global__ void __launch_bounds__(256) causal_kernel(
    const int* __restrict__ x, const float* __restrict__ cw,
    const float* __restrict__ cb, float* __restrict__ h)
{
    extern __shared__ float sm[];               // 32768 floats: cw [r][q][k]
    __shared__ float cbS[64];
    for (int i = threadIdx.x; i < NR * NQ * 2; i += 256) sm[i] = cw[i];
    if (threadIdx.x < 64) cbS[threadIdx.x] = cb[threadIdx.x];
    __syncthreads();
    int b = blockIdx.y;
    int t = blockIdx.x * 256 + threadIdx.x;
    if (t >= NT - 1) return;
    int q0 = x[b * NT + t] * 2;
    int q1 = x[b * NT + t + 1] * 2 + 1;
    float* hp = h + ((size_t)b << 20) + t;
    #pragma unroll 4
    for (int r = 0; r < 64; r++) {
        hp[r << 14] = sm[(r << 9) + q0] + sm[(r << 9) + q1] + cbS[r];
    }
}

// Fused WaveNet layer, 512 threads, 256 time cols per CTA.
// SMEM layout (floats):
//   [0, 8192)      wfT   (k,r,dc)   -- dead after phase1
//   [8192, 16384)  wgT   (k,r,dc)   -- dead after phase1
//   [0, 16448)     act   [64][257]  -- written after phase1 (overlaps wfT/wgT + 64 pad)
//   [16448, 20544) dwS   [r][dc]
//   [20544, 36928) hA    [64][256] h tap0  -- dead after phase1, reused for swS [s][dc]
//   [36928, 53312) hB    [64][256] h tap1
// total 53312 floats = 213248 B
__global__ void __launch_bounds__(512) layer_kernel(
    const float* __restrict__ hcur, float* __restrict__ hnext,
    const float* __restrict__ fw, const float* __restrict__ fb,
    const float* __restrict__ gw, const float* __restrict__ gb,
    const float* __restrict__ dw, const float* __restrict__ db,
    const float* __restrict__ sw, const float* __restrict__ sb,
    float* __restrict__ total,
    int dil, int Lh, int Ti, int off)
{
    extern __shared__ float smem[];
    float* wfT = smem;
    float* wgT = smem + 8192;
    float* act = smem;              // [64][257], valid after phase1
    float* dwS = smem + 16448;
    float* hA  = smem + 20544;      // later swS
    float* swS = smem + 20544;
    float* hB  = smem + 36928;

    const int tid = threadIdx.x;
    const int b = blockIdx.y;
    const int t0 = blockIdx.x * TT;

    // stage weights; fw/gw transposed to (k,r,dc) so inner reads are conflict-free
    #pragma unroll 1
    for (int i = tid; i < 8192; i += 512) {
        int dc = i >> 7, r = (i >> 1) & 63, k = i & 1;
        int si = (k << 12) + (r << 6) + dc;
        wfT[si] = fw[i];
        wgT[si] = gw[i];
    }
    for (int i = tid; i < 4096; i += 512) dwS[i] = dw[i];

    const float* hbase = hcur + ((size_t)b << 20);
    #pragma unroll 1
    for (int i = tid; i < 64 * TT; i += 512) {
        int r = i >> 8, tt = i & 255;
        int ta = t0 + tt;
        hA[i] = (ta < Lh) ? hbase[(r << 14) + ta] : 0.f;
        int tb = ta + dil;
        hB[i] = (tb < Lh) ? hbase[(r << 14) + tb] : 0.f;
    }
    __syncthreads();

    // ---- Phase 1: filter/gate GEMM (K=64, 2 taps) + activation ----
    const int dc = tid & 63;
    const int tg = tid >> 6;        // 0..7 : 32 time cols each
    float facc[32], gacc[32];
    {
        float fbv = fb[dc], gbv = gb[dc];
        #pragma unroll
        for (int j = 0; j < 32; j++) { facc[j] = fbv; gacc[j] = gbv; }
        const float* hap = hA + tg * 32;
        const float* hbp = hB + tg * 32;
        #pragma unroll 2
        for (int r = 0; r < 64; r++) {
            float wf0 = wfT[(r << 6) + dc];
            float wf1 = wfT[4096 + (r << 6) + dc];
            float wg0 = wgT[(r << 6) + dc];
            float wg1 = wgT[4096 + (r << 6) + dc];
            const float* ha = hap + (r << 8);
            const float* hb = hbp + (r << 8);
            #pragma unroll
            for (int j = 0; j < 32; j++) {
                float a = ha[j];
                float c = hb[j];
                facc[j] += wf0 * a;
                facc[j] += wf1 * c;
                gacc[j] += wg0 * a;
                gacc[j] += wg1 * c;
            }
        }
        // out = tanh(f) * sigmoid(g), via exp (clamped to avoid inf/NaN)
        #pragma unroll
        for (int j = 0; j < 32; j++) {
            float ef = __expf(fminf(-2.f * facc[j], 80.f));
            float th = __fdividef(1.f - ef, 1.f + ef);
            float eg = __expf(fminf(-gacc[j], 80.f));
            facc[j] = th * __fdividef(1.f, 1.f + eg);
        }
    }
    __syncthreads();    // all wfT/wgT/hA reads done

    // write activation tile; stage skip weights into dead hA region
    {
        float* row = act + dc * 257 + tg * 32;
        #pragma unroll
        for (int j = 0; j < 32; j++) row[j] = facc[j];
        #pragma unroll 1
        for (int i = tid; i < 16384; i += 512) swS[i] = sw[i];
    }
    __syncthreads();

    const int tl = tid & 31;
    const int wp = tid >> 5;   // 0..15

    // ---- Phase 2: dense 1x1 (D->R) + residual -> hnext ----
    {
        float acc[4][8];
        #pragma unroll
        for (int m = 0; m < 4; m++) {
            float dbv = db[wp + (m << 4)];
            #pragma unroll
            for (int q = 0; q < 8; q++) acc[m][q] = dbv;
        }
        #pragma unroll 1
        for (int dcc = 0; dcc < 64; dcc++) {
            const float* ar = act + dcc * 257 + tl;
            float o[8];
            #pragma unroll
            for (int q = 0; q < 8; q++) o[q] = ar[q << 5];
            #pragma unroll
            for (int m = 0; m < 4; m++) {
                float w = dwS[((wp + (m << 4)) << 6) + dcc];
                #pragma unroll
                for (int q = 0; q < 8; q++) acc[m][q] += w * o[q];
            }
        }
        float* hnb = hnext + ((size_t)b << 20);
        #pragma unroll
        for (int m = 0; m < 4; m++) {
            int r = wp + (m << 4);
            #pragma unroll
            for (int q = 0; q < 8; q++) {
                int tt = tl + (q << 5);
                int tgl = t0 + tt;
                if (tgl < Ti) hnb[(r << 14) + tgl] = hB[(r << 8) + tt] + acc[m][q];
            }
        }
    }

    // ---- Phase 3: skip 1x1 (D->S), RMW into total (lane-contiguous in time) ----
    #pragma unroll 1
    for (int half = 0; half < 2; half++) {
        float acc[16][4];
        #pragma unroll
        for (int m = 0; m < 16; m++)
            #pragma unroll
            for (int q = 0; q < 4; q++) acc[m][q] = 0.f;
        #pragma unroll 1
        for (int dcc = 0; dcc < 64; dcc++) {
            const float* ar = act + dcc * 257 + (half << 7) + tl;
            float o0 = ar[0];
            float o1 = ar[32];
            float o2 = ar[64];
            float o3 = ar[96];
            #pragma unroll
            for (int m = 0; m < 16; m++) {
                float w = swS[((wp + (m << 4)) << 6) + dcc];
                acc[m][0] += w * o0;
                acc[m][1] += w * o1;
                acc[m][2] += w * o2;
                acc[m][3] += w * o3;
            }
        }
        #pragma unroll
        for (int m = 0; m < 16; m++) {
            int s = wp + (m << 4);
            float sbv = sb[s];
            float* tb2 = total + (size_t)((b << 8) + s) * OUTW_PAD - off;
            #pragma unroll
            for (int q = 0; q < 4; q++) {
                int tgl = t0 + (half << 7) + tl + (q << 5);
                if (tgl >= off && tgl < Ti) tb2[tgl] += acc[m][q] + sbv;
            }
        }
    }
}

// out[b][s][t] = bias[s] + sum_k wT[k][s] * relu(in[b][k][t])   (256x256 GEMM)
// 512 threads, 128-col tile. smem: inS [256][128] + wS [64][256] = 49152 floats
__global__ void __launch_bounds__(512) post_kernel(
    const float* __restrict__ in, const float* __restrict__ wT,
    const float* __restrict__ bias, float* __restrict__ outp, int ostride)
{
    extern __shared__ float smem[];
    float* inS = smem;            // [256][128]
    float* wS  = smem + 32768;    // [64][256] staged per k-chunk
    const int tid = threadIdx.x;
    const int b = blockIdx.y;
    const int t0 = blockIdx.x << 7;

    #pragma unroll 1
    for (int i = tid; i < 32768; i += 512) {
        int k = i >> 7, tt = i & 127;
        int t = t0 + tt;
        float v = (t < OUTW) ? in[(size_t)((b << 8) + k) * OUTW_PAD + t] : 0.f;
        inS[i] = fmaxf(v, 0.f);
    }
    const int tl = tid & 31;
    const int wp = tid >> 5;   // 0..15
    float acc[16][4];
    #pragma unroll
    for (int m = 0; m < 16; m++) {
        float bv = bias[wp + (m << 4)];
        #pragma unroll
        for (int q = 0; q < 4; q++) acc[m][q] = bv;
    }
    #pragma unroll 1
    for (int kc = 0; kc < 4; kc++) {
        __syncthreads();
        #pragma unroll 1
        for (int i = tid; i < 16384; i += 512) wS[i] = wT[(kc << 14) + i];
        __syncthreads();
        #pragma unroll 1
        for (int kk = 0; kk < 64; kk++) {
            const float* ir = inS + (((kc << 6) + kk) << 7) + tl;
            float v0 = ir[0];
            float v1 = ir[32];
            float v2 = ir[64];
            float v3 = ir[96];
            #pragma unroll
            for (int m = 0; m < 16; m++) {
                float w = wS[(kk << 8) + wp + (m << 4)];
                acc[m][0] += w * v0;
                acc[m][1] += w * v1;
                acc[m][2] += w * v2;
                acc[m][3] += w * v3;
            }
        }
    }
    #pragma unroll
    for (int m = 0; m < 16; m++) {
        int s = wp + (m << 4);
        float* op = outp + (size_t)((b << 8) + s) * ostride + t0;
        #pragma unroll
        for (int q = 0; q < 4; q++) {
            int tt = tl + (q << 5);
            if (t0 + tt < OUTW) op[tt] = acc[m][q];
        }
    }
}

extern "C" void kernel_launch(void* const* d_in, const int* in_sizes, int n_in,
                              void* d_out, int out_size)
{
    const int*   x        = (const int*)d_in[0];
    const float* causal_w = (const float*)d_in[1];
    const float* causal_b = (const float*)d_in[2];
    const float* filt_w   = (const float*)d_in[3];
    const float* filt_b   = (const float*)d_in[4];
    const float* gate_w   = (const float*)d_in[5];
    const float* gate_b   = (const float*)d_in[6];
    const float* dense_w  = (const float*)d_in[7];
    const float* dense_b  = (const float*)d_in[8];
    const float* skip_w   = (const float*)d_in[9];
    const float* skip_b   = (const float*)d_in[10];
    const float* pp1_w    = (const float*)d_in[11];
    const float* pp1_b    = (const float*)d_in[12];
    const float* pp2_w    = (const float*)d_in[13];
    const float* pp2_b    = (const float*)d_in[14];
    float* out = (float*)d_out;

    float *h0, *h1, *total, *c1, *w1T, *w2T;
    cudaGetSymbolAddress((void**)&h0, g_h0);
    cudaGetSymbolAddress((void**)&h1, g_h1);
    cudaGetSymbolAddress((void**)&total, g_total);
    cudaGetSymbolAddress((void**)&c1, g_c1);
    cudaGetSymbolAddress((void**)&w1T, g_w1T);
    cudaGetSymbolAddress((void**)&w2T, g_w2T);

    static const int dil[NL] = {1, 2, 4, 8, 16, 32, 64, 128, 256, 512,
                                1, 2, 4, 8, 16, 32, 64, 128, 256, 512};

    cudaFuncSetAttribute(layer_kernel,  cudaFuncAttributeMaxDynamicSharedMemorySize, 53312 * 4);
    cudaFuncSetAttribute(causal_kernel, cudaFuncAttributeMaxDynamicSharedMemorySize, 32768 * 4);
    cudaFuncSetAttribute(post_kernel,   cudaFuncAttributeMaxDynamicSharedMemorySize, 49152 * 4);

    int nTot = NB * NS * OUTW_PAD;
    zero_kernel<<<(nTot + 255) / 256, 256>>>(total, nTot);

    dim3 cg((NT - 1 + 255) / 256, NB);
    causal_kernel<<<cg, 256, 32768 * 4>>>(x, causal_w, causal_b, h0);

    float* hc = h0;
    float* hn = h1;
    int Lh = NT - 1;
    for (int i = 0; i < NL; i++) {
        int d = dil[i];
        int Ti = Lh - d;
        int off = Ti - OUTW;
        dim3 g((Ti + TT - 1) / TT, NB);
        layer_kernel<<<g, 512, 53312 * 4>>>(
            hc, hn,
            filt_w + (size_t)i * ND * NR * 2, filt_b + (size_t)i * ND,
            gate_w + (size_t)i * ND * NR * 2, gate_b + (size_t)i * ND,
            dense_w + (size_t)i * NR * ND,    dense_b + (size_t)i * NR,
            skip_w + (size_t)i * NS * ND,     skip_b + (size_t)i * NS,
            total, d, Lh, Ti, off);
        float* tmp = hc; hc = hn; hn = tmp;
        Lh = Ti;
    }

    transpose_kernel<<<256, 256>>>(pp1_w, w1T);
    transpose_kernel<<<256, 256>>>(pp2_w, w2T);

    dim3 pg((OUTW + 127) / 128, NB);
    post_kernel<<<pg, 512, 49152 * 4>>>(total, w1T, pp1_b, c1, OUTW_PAD);
    post_kernel<<<pg, 512, 49152 * 4>>>(c1, w2T, pp2_b, out, OUTW);
}

// round 3
// speedup vs baseline: 2.0700x; 1.1739x over previous
#include <cuda_runtime.h>
#include <math.h>

#define NB 8
#define NT 16384
#define NQ 256
#define NR 64
#define ND 64
#define NS 256
#define NL 20
#define OUTW 14337
#define OUTW_PAD 14368
#define TT 256
#define AS 258   // padded row stride for act / swT

typedef unsigned long long ull;

__device__ __forceinline__ ull pack2(float x) {
    ull r; asm("mov.b64 %0, {%1, %1};" : "=l"(r) : "f"(x)); return r;
}
__device__ __forceinline__ ull pack2(float lo, float hi) {
    ull r; asm("mov.b64 %0, {%1, %2};" : "=l"(r) : "f"(lo), "f"(hi)); return r;
}
__device__ __forceinline__ void fma2(ull& d, ull a, ull b) {
    asm("fma.rn.f32x2 %0, %1, %2, %0;" : "+l"(d) : "l"(a), "l"(b));
}
__device__ __forceinline__ float2 u2f(ull v) {
    float2 f; asm("mov.b64 {%0, %1}, %2;" : "=f"(f.x), "=f"(f.y) : "l"(v)); return f;
}

// Scratch (device globals; no allocation allowed)
__device__ float g_h0[NB * NR * NT];
__device__ float g_h1[NB * NR * NT];
__device__ float g_total[NB * NS * OUTW_PAD];
__device__ float g_c1[NB * NS * OUTW_PAD];
__device__ float g_w1T[NS * NS];
__device__ float g_w2T[NQ * NS];

__global__ void zero_kernel(float* __restrict__ p, int n) {
    int i = blockIdx.x * blockDim.x + threadIdx.x;
    if (i < n) p[i] = 0.f;
}

// wT[k][s] = w[s][k], 256x256
__global__ void transpose_kernel(const float* __restrict__ w, float* __restrict__ wT) {
    int i = blockIdx.x * 256 + threadIdx.x;
    int k = i >> 8, s = i & 255;
    wT[i] = w[(s << 8) + k];
}

// h[b][r][t] = cw[r][x[b,t]][0] + cw[r][x[b,t+1]][1] + cb[r]   (one-hot conv == gather)
__global__ void __launch_bounds__(256) causal_kernel(
    const int* __restrict__ x, const float* __restrict__ cw,
    const float* __restrict__ cb, float* __restrict__ h)
{
    extern __shared__ float sm[];               // 32768 floats: cw [r][q][k]
    __shared__ float cbS[64];
    for (int i = threadIdx.x; i < NR * NQ * 2; i += 256) sm[i] = cw[i];
    if (threadIdx.x < 64) cbS[threadIdx.x] = cb[threadIdx.x];
    __syncthreads();
    int b = blockIdx.y;
    int t = blockIdx.x * 256 + threadIdx.x;
    if (t >= NT - 1) return;
    int q0 = x[b * NT + t] * 2;
    int q1 = x[b * NT + t + 1] * 2 + 1;
    float* hp = h + ((size_t)b << 20) + t;
    #pragma unroll 4
    for (int r = 0; r < 64; r++) {
        hp[r << 14] = sm[(r << 9) + q0] + sm[(r << 9) + q1] + cbS[r];
    }
}

// Fused WaveNet layer, 512 threads, 256 time cols per CTA, packed f32x2 math.
// SMEM layout (floats):
//   [0, 8192)        wfT (k,r,dc)       -- dead after phase1
//   [8192, 16384)    wgT (k,r,dc)       -- dead after phase1
//   [0, 16512)       act [64][258]      -- written after phase1 (overlaps wfT/wgT)
//   [16512, 20608)   dwS [r][dc]
//   [20608, 36992)   hA  [64][256]      -- dead after phase1
//   [20608, 37120)   swT [dc][258]      -- staged after phase1 into hA region
//   [37120, 53504)   hB  [64][256]
// total 53504 floats = 214016 B
__global__ void __launch_bounds__(512) layer_kernel(
    const float* __restrict__ hcur, float* __restrict__ hnext,
    const float* __restrict__ fw, const float* __restrict__ fb,
    const float* __restrict__ gw, const float* __restrict__ gb,
    const float* __restrict__ dw, const float* __restrict__ db,
    const float* __restrict__ sw, const float* __restrict__ sb,
    float* __restrict__ total,
    int dil, int Lh, int Ti, int off)
{
    extern __shared__ float smem[];
    float* wfT = smem;
    float* wgT = smem + 8192;
    float* act = smem;              // [64][258], valid after phase1
    float* dwS = smem + 16512;
    float* hA  = smem + 20608;
    float* swT = smem + 20608;      // [64][258] transposed skip weights, after phase1
    float* hB  = smem + 37120;

    const int tid = threadIdx.x;
    const int b = blockIdx.y;
    const int t0 = blockIdx.x * TT;

    // stage weights; fw/gw transposed to (k,r,dc) so inner reads are conflict-free
    #pragma unroll 1
    for (int i = tid; i < 8192; i += 512) {
        int dc = i >> 7, r = (i >> 1) & 63, k = i & 1;
        int si = (k << 12) + (r << 6) + dc;
        wfT[si] = fw[i];
        wgT[si] = gw[i];
    }
    for (int i = tid; i < 4096; i += 512) dwS[i] = dw[i];

    const float* hbase = hcur + ((size_t)b << 20);
    #pragma unroll 1
    for (int i = tid; i < 64 * TT; i += 512) {
        int r = i >> 8, tt = i & 255;
        int ta = t0 + tt;
        hA[i] = (ta < Lh) ? hbase[(r << 14) + ta] : 0.f;
        int tb = ta + dil;
        hB[i] = (tb < Lh) ? hbase[(r << 14) + tb] : 0.f;
    }
    __syncthreads();

    // ---- Phase 1: filter/gate GEMM (K=64, 2 taps), time-packed f32x2 ----
    const int dc = tid & 63;
    const int tg = tid >> 6;        // 0..7 : 32 time cols each
    ull facc2[16], gacc2[16];
    {
        ull fb2 = pack2(fb[dc]);
        ull gb2 = pack2(gb[dc]);
        #pragma unroll
        for (int j = 0; j < 16; j++) { facc2[j] = fb2; gacc2[j] = gb2; }
        const float* hap = hA + (tg << 5);
        const float* hbp = hB + (tg << 5);
        #pragma unroll 2
        for (int r = 0; r < 64; r++) {
            ull wf0 = pack2(wfT[(r << 6) + dc]);
            ull wf1 = pack2(wfT[4096 + (r << 6) + dc]);
            ull wg0 = pack2(wgT[(r << 6) + dc]);
            ull wg1 = pack2(wgT[4096 + (r << 6) + dc]);
            const float* ha = hap + (r << 8);
            const float* hb = hbp + (r << 8);
            #pragma unroll
            for (int j = 0; j < 8; j++) {
                ulonglong2 A = *(const ulonglong2*)(ha + (j << 2));
                ulonglong2 C = *(const ulonglong2*)(hb + (j << 2));
                fma2(facc2[2*j],   wf0, A.x);
                fma2(facc2[2*j+1], wf0, A.y);
                fma2(facc2[2*j],   wf1, C.x);
                fma2(facc2[2*j+1], wf1, C.y);
                fma2(gacc2[2*j],   wg0, A.x);
                fma2(gacc2[2*j+1], wg0, A.y);
                fma2(gacc2[2*j],   wg1, C.x);
                fma2(gacc2[2*j+1], wg1, C.y);
            }
        }
        // out = tanh(f) * sigmoid(g)
        #pragma unroll
        for (int j = 0; j < 16; j++) {
            float2 f = u2f(facc2[j]);
            float2 g = u2f(gacc2[j]);
            float ef0 = __expf(fminf(-2.f * f.x, 80.f));
            float ef1 = __expf(fminf(-2.f * f.y, 80.f));
            float eg0 = __expf(fminf(-g.x, 80.f));
            float eg1 = __expf(fminf(-g.y, 80.f));
            float o0 = __fdividef(1.f - ef0, (1.f + ef0) * (1.f + eg0));
            float o1 = __fdividef(1.f - ef1, (1.f + ef1) * (1.f + eg1));
            facc2[j] = pack2(o0, o1);
        }
    }
    __syncthreads();    // all wfT/wgT/hA reads done

    // write activation tile; stage transposed skip weights into dead hA region
    {
        float* row = act + dc * AS + (tg << 5);
        #pragma unroll
        for (int j = 0; j < 16; j++)
            *(float2*)(row + (j << 1)) = u2f(facc2[j]);
        // swT[dc][s] = sw[s][dc]; coalesced global reads, 2-way STS conflicts
        #pragma unroll 1
        for (int i = tid; i < 16384; i += 512)
            swT[(i & 63) * AS + (i >> 6)] = sw[i];
    }
    __syncthreads();

    const int tl = tid & 31;
    const int wp = tid >> 5;   // 0..15

    // ---- Phase 2: dense 1x1 (D->R) + residual -> hnext, time-packed ----
    {
        ull acc[4][4];
        #pragma unroll
        for (int m = 0; m < 4; m++) {
            ull dbv = pack2(db[wp + (m << 4)]);
            #pragma unroll
            for (int p = 0; p < 4; p++) acc[m][p] = dbv;
        }
        #pragma unroll 1
        for (int dcc = 0; dcc < 64; dcc++) {
            const float* ar = act + dcc * AS + (tl << 1);
            ull o[4];
            #pragma unroll
            for (int p = 0; p < 4; p++) o[p] = *(const ull*)(ar + (p << 6));
            #pragma unroll
            for (int m = 0; m < 4; m++) {
                ull w = pack2(dwS[((wp + (m << 4)) << 6) + dcc]);
                #pragma unroll
                for (int p = 0; p < 4; p++) fma2(acc[m][p], w, o[p]);
            }
        }
        float* hnb = hnext + ((size_t)b << 20);
        #pragma unroll
        for (int m = 0; m < 4; m++) {
            int r = wp + (m << 4);
            #pragma unroll
            for (int p = 0; p < 4; p++) {
                int tt = (tl << 1) + (p << 6);
                int tgl = t0 + tt;
                float2 hv = *(const float2*)(hB + (r << 8) + tt);
                float2 v = u2f(acc[m][p]);
                v.x += hv.x; v.y += hv.y;
                if (tgl + 1 < Ti) {
                    *(float2*)(hnb + (r << 14) + tgl) = v;
                } else if (tgl < Ti) {
                    hnb[(r << 14) + tgl] = v.x;
                }
            }
        }
    }

    // ---- Phase 3: skip 1x1 (D->S), channel-packed, RMW into total ----
    #pragma unroll 1
    for (int half = 0; half < 2; half++) {
        ull acc[8][4];
        #pragma unroll
        for (int mp = 0; mp < 8; mp++)
            #pragma unroll
            for (int q = 0; q < 4; q++) acc[mp][q] = 0ULL;
        #pragma unroll 1
        for (int dcc = 0; dcc < 64; dcc++) {
            const float* ar = act + dcc * AS + (half << 7) + tl;
            ull o[4];
            #pragma unroll
            for (int q = 0; q < 4; q++) o[q] = pack2(ar[q << 5]);
            const float* wr = swT + dcc * AS + (wp << 1);
            #pragma unroll
            for (int mp = 0; mp < 8; mp++) {
                ull w = *(const ull*)(wr + (mp << 5));
                #pragma unroll
                for (int q = 0; q < 4; q++) fma2(acc[mp][q], w, o[q]);
            }
        }
        #pragma unroll
        for (int mp = 0; mp < 8; mp++) {
            int s0 = (wp << 1) + (mp << 5);
            float sb0 = sb[s0], sb1 = sb[s0 + 1];
            float* tb0 = total + (size_t)((b << 8) + s0) * OUTW_PAD - off;
            float* tb1 = tb0 + OUTW_PAD;
            #pragma unroll
            for (int q = 0; q < 4; q++) {
                int tgl = t0 + (half << 7) + tl + (q << 5);
                if (tgl >= off && tgl < Ti) {
                    float2 v = u2f(acc[mp][q]);
                    tb0[tgl] += v.x + sb0;
                    tb1[tgl] += v.y + sb1;
                }
            }
        }
    }
}

// out[b][s][t] = bias[s] + sum_k wT[k][s] * relu(in[b][k][t])   (256x256 GEMM)
// 512 threads, 128-col tile, channel-packed f32x2.
// smem: inS [256][128] + wS [64][256] = 49152 floats
__global__ void __launch_bounds__(512) post_kernel(
    const float* __restrict__ in, const float* __restrict__ wT,
    const float* __restrict__ bias, float* __restrict__ outp, int ostride)
{
    extern __shared__ float smem[];
    float* inS = smem;            // [256][128]
    float* wS  = smem + 32768;    // [64][256] staged per k-chunk (s contiguous)
    const int tid = threadIdx.x;
    const int b = blockIdx.y;
    const int t0 = blockIdx.x << 7;

    #pragma unroll 1
    for (int i = tid; i < 32768; i += 512) {
        int k = i >> 7, tt = i & 127;
        int t = t0 + tt;
        float v = (t < OUTW) ? in[(size_t)((b << 8) + k) * OUTW_PAD + t] : 0.f;
        inS[i] = fmaxf(v, 0.f);
    }
    const int tl = tid & 31;
    const int wp = tid >> 5;   // 0..15
    ull acc[8][4];
    #pragma unroll
    for (int mp = 0; mp < 8; mp++) {
        int s0 = (wp << 1) + (mp << 5);
        ull bv = pack2(bias[s0], bias[s0 + 1]);
        #pragma unroll
        for (int q = 0; q < 4; q++) acc[mp][q] = bv;
    }
    #pragma unroll 1
    for (int kc = 0; kc < 4; kc++) {
        __syncthreads();
        #pragma unroll 1
        for (int i = tid; i < 16384; i += 512) wS[i] = wT[(kc << 14) + i];
        __syncthreads();
        #pragma unroll 1
        for (int kk = 0; kk < 64; kk++) {
            const float* ir = inS + (((kc << 6) + kk) << 7) + tl;
            ull o[4];
            #pragma unroll
            for (int q = 0; q < 4; q++) o[q] = pack2(ir[q << 5]);
            const float* wr = wS + (kk << 8) + (wp << 1);
            #pragma unroll
            for (int mp = 0; mp < 8; mp++) {
                ull w = *(const ull*)(wr + (mp << 5));
                #pragma unroll
                for (int q = 0; q < 4; q++) fma2(acc[mp][q], w, o[q]);
            }
        }
    }
    #pragma unroll
    for (int mp = 0; mp < 8; mp++) {
        int s0 = (wp << 1) + (mp << 5);
        float* op0 = outp + (size_t)((b << 8) + s0) * ostride + t0;
        float* op1 = op0 + ostride;
        #pragma unroll
        for (int q = 0; q < 4; q++) {
            int tt = tl + (q << 5);
            if (t0 + tt < OUTW) {
                float2 v = u2f(acc[mp][q]);
                op0[tt] = v.x;
                op1[tt] = v.y;
            }
        }
    }
}

extern "C" void kernel_launch(void* const* d_in, const int* in_sizes, int n_in,
                              void* d_out, int out_size)
{
    const int*   x        = (const int*)d_in[0];
    const float* causal_w = (const float*)d_in[1];
    const float* causal_b = (const float*)d_in[2];
    const float* filt_w   = (const float*)d_in[3];
    const float* filt_b   = (const float*)d_in[4];
    const float* gate_w   = (const float*)d_in[5];
    const float* gate_b   = (const float*)d_in[6];
    const float* dense_w  = (const float*)d_in[7];
    const float* dense_b  = (const float*)d_in[8];
    const float* skip_w   = (const float*)d_in[9];
    const float* skip_b   = (const float*)d_in[10];
    const float* pp1_w    = (const float*)d_in[11];
    const float* pp1_b    = (const float*)d_in[12];
    const float* pp2_w    = (const float*)d_in[13];
    const float* pp2_b    = (const float*)d_in[14];
    float* out = (float*)d_out;

    float *h0, *h1, *total, *c1, *w1T, *w2T;
    cudaGetSymbolAddress((void**)&h0, g_h0);
    cudaGetSymbolAddress((void**)&h1, g_h1);
    cudaGetSymbolAddress((void**)&total, g_total);
    cudaGetSymbolAddress((void**)&c1, g_c1);
    cudaGetSymbolAddress((void**)&w1T, g_w1T);
    cudaGetSymbolAddress((void**)&w2T, g_w2T);

    static const int dil[NL] = {1, 2, 4, 8, 16, 32, 64, 128, 256, 512,
                                1, 2, 4, 8, 16, 32, 64, 128, 256, 512};

    cudaFuncSetAttribute(layer_kernel,  cudaFuncAttributeMaxDynamicSharedMemorySize, 53504 * 4);
    cudaFuncSetAttribute(causal_kernel, cudaFuncAttributeMaxDynamicSharedMemorySize, 32768 * 4);
    cudaFuncSetAttribute(post_kernel,   cudaFuncAttributeMaxDynamicSharedMemorySize, 49152 * 4);

    int nTot = NB * NS * OUTW_PAD;
    zero_kernel<<<(nTot + 255) / 256, 256>>>(total, nTot);

    dim3 cg((NT - 1 + 255) / 256, NB);
    causal_kernel<<<cg, 256, 32768 * 4>>>(x, causal_w, causal_b, h0);

    float* hc = h0;
    float* hn = h1;
    int Lh = NT - 1;
    for (int i = 0; i < NL; i++) {
        int d = dil[i];
        int Ti = Lh - d;
        int off = Ti - OUTW;
        dim3 g((Ti + TT - 1) / TT, NB);
        layer_kernel<<<g, 512, 53504 * 4>>>(
            hc, hn,
            filt_w + (size_t)i * ND * NR * 2, filt_b + (size_t)i * ND,
            gate_w + (size_t)i * ND * NR * 2, gate_b + (size_t)i * ND,
            dense_w + (size_t)i * NR * ND,    dense_b + (size_t)i * NR,
            skip_w + (size_t)i * NS * ND,     skip_b + (size_t)i * NS,
            total, d, Lh, Ti, off);
        float* tmp = hc; hc = hn; hn = tmp;
        Lh = Ti;
    }

    transpose_kernel<<<256, 256>>>(pp1_w, w1T);
    transpose_kernel<<<256, 256>>>(pp2_w, w2T);

    dim3 pg((OUTW + 127) / 128, NB);
    post_kernel<<<pg, 512, 49152 * 4>>>(total, w1T, pp1_b, c1, OUTW_PAD);
    post_kernel<<<pg, 512, 49152 * 4>>>(c1, w2T, pp2_b, out, OUTW);
}

// round 4
// speedup vs baseline: 2.4863x; 1.2011x over previous
#include <cuda_runtime.h>
#include <math.h>

#define NB 8
#define NT 16384
#define NQ 256
#define NR 64
#define ND 64
#define NS 256
#define NL 20
#define OUTW 14337
#define OUTW_PAD 14368
#define TT 256
#define AS 258   // padded row stride for act / swT

typedef unsigned long long ull;

__device__ __forceinline__ ull pack2(float x) {
    ull r; asm("mov.b64 %0, {%1, %1};" : "=l"(r) : "f"(x)); return r;
}
__device__ __forceinline__ ull pack2(float lo, float hi) {
    ull r; asm("mov.b64 %0, {%1, %2};" : "=l"(r) : "f"(lo), "f"(hi)); return r;
}
__device__ __forceinline__ void fma2(ull& d, ull a, ull b) {
    asm("fma.rn.f32x2 %0, %1, %2, %0;" : "+l"(d) : "l"(a), "l"(b));
}
__device__ __forceinline__ float2 u2f(ull v) {
    float2 f; asm("mov.b64 {%0, %1}, %2;" : "=f"(f.x), "=f"(f.y) : "l"(v)); return f;
}

// Scratch (device globals; no allocation allowed)
__device__ float g_h0[NB * NR * NT];
__device__ float g_h1[NB * NR * NT];
__device__ float g_total[NB * NS * OUTW_PAD];
__device__ float g_c1[NB * NS * OUTW_PAD];
__device__ float g_w1T[NS * NS];
__device__ float g_w2T[NQ * NS];

__global__ void zero_kernel(float* __restrict__ p, int n) {
    int i = blockIdx.x * blockDim.x + threadIdx.x;
    if (i < n) p[i] = 0.f;
}

// wT[k][s] = w[s][k], 256x256
__global__ void transpose_kernel(const float* __restrict__ w, float* __restrict__ wT) {
    int i = blockIdx.x * 256 + threadIdx.x;
    int k = i >> 8, s = i & 255;
    wT[i] = w[(s << 8) + k];
}

// h[b][r][t] = cw[r][x[b,t]][0] + cw[r][x[b,t+1]][1] + cb[r]   (one-hot conv == gather)
__global__ void __launch_bounds__(256) causal_kernel(
    const int* __restrict__ x, const float* __restrict__ cw,
    const float* __restrict__ cb, float* __restrict__ h)
{
    extern __shared__ float sm[];               // 32768 floats: cw [r][q][k]
    __shared__ float cbS[64];
    for (int i = threadIdx.x; i < NR * NQ * 2; i += 256) sm[i] = cw[i];
    if (threadIdx.x < 64) cbS[threadIdx.x] = cb[threadIdx.x];
    __syncthreads();
    int b = blockIdx.y;
    int t = blockIdx.x * 256 + threadIdx.x;
    if (t >= NT - 1) return;
    int q0 = x[b * NT + t] * 2;
    int q1 = x[b * NT + t + 1] * 2 + 1;
    float* hp = h + ((size_t)b << 20) + t;
    #pragma unroll 4
    for (int r = 0; r < 64; r++) {
        hp[r << 14] = sm[(r << 9) + q0] + sm[(r << 9) + q1] + cbS[r];
    }
}

// Fused WaveNet layer, 1024 threads (32 warps), 256 time cols per CTA, f32x2 math.
// SMEM layout (floats):
//   [0, 8192)        wfT (k,r,dc)       -- dead after phase1
//   [8192, 16384)    wgT (k,r,dc)       -- dead after phase1
//   [0, 16512)       act [64][258]      -- written after phase1 (overlaps wfT/wgT)
//   [16512, 20608)   dwS [r][dc]
//   [20608, 36992)   hA  [64][256]      -- dead after phase1
//   [20608, 37120)   swT [dc][258]      -- staged after phase1 into hA region
//   [37120, 53504)   hB  [64][256]
// total 53504 floats = 214016 B
__global__ void __launch_bounds__(1024) layer_kernel(
    const float* __restrict__ hcur, float* __restrict__ hnext,
    const float* __restrict__ fw, const float* __restrict__ fb,
    const float* __restrict__ gw, const float* __restrict__ gb,
    const float* __restrict__ dw, const float* __restrict__ db,
    const float* __restrict__ sw, const float* __restrict__ sb,
    float* __restrict__ total,
    int dil, int Lh, int Ti, int off)
{
    extern __shared__ float smem[];
    float* wfT = smem;
    float* wgT = smem + 8192;
    float* act = smem;              // [64][258], valid after phase1
    float* dwS = smem + 16512;
    float* hA  = smem + 20608;
    float* swT = smem + 20608;      // [64][258] transposed skip weights, after phase1
    float* hB  = smem + 37120;

    const int tid = threadIdx.x;
    const int b = blockIdx.y;
    const int t0 = blockIdx.x * TT;

    // stage weights; fw/gw transposed to (k,r,dc) so inner reads are conflict-free
    #pragma unroll 1
    for (int i = tid; i < 8192; i += 1024) {
        int dcq = i >> 7, r = (i >> 1) & 63, k = i & 1;
        int si = (k << 12) + (r << 6) + dcq;
        wfT[si] = fw[i];
        wgT[si] = gw[i];
    }
    for (int i = tid; i < 4096; i += 1024) dwS[i] = dw[i];

    const float* hbase = hcur + ((size_t)b << 20);
    #pragma unroll 1
    for (int i = tid; i < 64 * TT; i += 1024) {
        int r = i >> 8, tt = i & 255;
        int ta = t0 + tt;
        hA[i] = (ta < Lh) ? hbase[(r << 14) + ta] : 0.f;
        int tb = ta + dil;
        hB[i] = (tb < Lh) ? hbase[(r << 14) + tb] : 0.f;
    }
    __syncthreads();

    // ---- Phase 1: filter/gate GEMM (K=64, 2 taps), 16 time cols/thread ----
    const int dc = tid & 63;
    const int tg = tid >> 6;        // 0..15 : 16 time cols each
    ull facc2[8], gacc2[8];
    {
        ull fb2 = pack2(fb[dc]);
        ull gb2 = pack2(gb[dc]);
        #pragma unroll
        for (int j = 0; j < 8; j++) { facc2[j] = fb2; gacc2[j] = gb2; }
        const float* hap = hA + (tg << 4);
        const float* hbp = hB + (tg << 4);
        #pragma unroll 2
        for (int r = 0; r < 64; r++) {
            ull wf0 = pack2(wfT[(r << 6) + dc]);
            ull wf1 = pack2(wfT[4096 + (r << 6) + dc]);
            ull wg0 = pack2(wgT[(r << 6) + dc]);
            ull wg1 = pack2(wgT[4096 + (r << 6) + dc]);
            const float* ha = hap + (r << 8);
            const float* hb = hbp + (r << 8);
            #pragma unroll
            for (int j = 0; j < 4; j++) {
                ulonglong2 A = *(const ulonglong2*)(ha + (j << 2));
                ulonglong2 C = *(const ulonglong2*)(hb + (j << 2));
                fma2(facc2[2*j],   wf0, A.x);
                fma2(facc2[2*j+1], wf0, A.y);
                fma2(facc2[2*j],   wf1, C.x);
                fma2(facc2[2*j+1], wf1, C.y);
                fma2(gacc2[2*j],   wg0, A.x);
                fma2(gacc2[2*j+1], wg0, A.y);
                fma2(gacc2[2*j],   wg1, C.x);
                fma2(gacc2[2*j+1], wg1, C.y);
            }
        }
        // out = tanh(f) * sigmoid(g)
        #pragma unroll
        for (int j = 0; j < 8; j++) {
            float2 f = u2f(facc2[j]);
            float2 g = u2f(gacc2[j]);
            float ef0 = __expf(fminf(-2.f * f.x, 80.f));
            float ef1 = __expf(fminf(-2.f * f.y, 80.f));
            float eg0 = __expf(fminf(-g.x, 80.f));
            float eg1 = __expf(fminf(-g.y, 80.f));
            float o0 = __fdividef(1.f - ef0, (1.f + ef0) * (1.f + eg0));
            float o1 = __fdividef(1.f - ef1, (1.f + ef1) * (1.f + eg1));
            facc2[j] = pack2(o0, o1);
        }
    }
    __syncthreads();    // all wfT/wgT/hA reads done

    // write activation tile; stage transposed skip weights into dead hA region
    {
        float* row = act + dc * AS + (tg << 4);
        #pragma unroll
        for (int j = 0; j < 8; j++)
            *(float2*)(row + (j << 1)) = u2f(facc2[j]);
        // swT[dc][s] = sw[s][dc]; coalesced global reads
        #pragma unroll 1
        for (int i = tid; i < 16384; i += 1024)
            swT[(i & 63) * AS + (i >> 6)] = sw[i];
    }
    __syncthreads();

    const int tl = tid & 31;
    const int wp = tid >> 5;   // 0..31

    // ---- Phase 2: dense 1x1 (D->R) + residual -> hnext, time-packed ----
    {
        ull acc[2][4];
        #pragma unroll
        for (int m = 0; m < 2; m++) {
            ull dbv = pack2(db[wp + (m << 5)]);
            #pragma unroll
            for (int p = 0; p < 4; p++) acc[m][p] = dbv;
        }
        #pragma unroll 1
        for (int dcc = 0; dcc < 64; dcc++) {
            const float* ar = act + dcc * AS + (tl << 1);
            ull o[4];
            #pragma unroll
            for (int p = 0; p < 4; p++) o[p] = *(const ull*)(ar + (p << 6));
            #pragma unroll
            for (int m = 0; m < 2; m++) {
                ull w = pack2(dwS[((wp + (m << 5)) << 6) + dcc]);
                #pragma unroll
                for (int p = 0; p < 4; p++) fma2(acc[m][p], w, o[p]);
            }
        }
        float* hnb = hnext + ((size_t)b << 20);
        #pragma unroll
        for (int m = 0; m < 2; m++) {
            int r = wp + (m << 5);
            #pragma unroll
            for (int p = 0; p < 4; p++) {
                int tt = (tl << 1) + (p << 6);
                int tgl = t0 + tt;
                float2 hv = *(const float2*)(hB + (r << 8) + tt);
                float2 v = u2f(acc[m][p]);
                v.x += hv.x; v.y += hv.y;
                if (tgl + 1 < Ti) {
                    *(float2*)(hnb + (r << 14) + tgl) = v;
                } else if (tgl < Ti) {
                    hnb[(r << 14) + tgl] = v.x;
                }
            }
        }
    }

    // ---- Phase 3: skip 1x1 (D->S), channel-packed, RMW into total ----
    #pragma unroll 1
    for (int half = 0; half < 2; half++) {
        ull acc[4][4];
        #pragma unroll
        for (int mp = 0; mp < 4; mp++)
            #pragma unroll
            for (int q = 0; q < 4; q++) acc[mp][q] = 0ULL;
        #pragma unroll 1
        for (int dcc = 0; dcc < 64; dcc++) {
            const float* ar = act + dcc * AS + (half << 7) + tl;
            ull o[4];
            #pragma unroll
            for (int q = 0; q < 4; q++) o[q] = pack2(ar[q << 5]);
            const float* wr = swT + dcc * AS + (wp << 1);
            #pragma unroll
            for (int mp = 0; mp < 4; mp++) {
                ull w = *(const ull*)(wr + (mp << 6));
                #pragma unroll
                for (int q = 0; q < 4; q++) fma2(acc[mp][q], w, o[q]);
            }
        }
        #pragma unroll
        for (int mp = 0; mp < 4; mp++) {
            int s0 = (wp << 1) + (mp << 6);
            float sb0 = sb[s0], sb1 = sb[s0 + 1];
            float* tb0 = total + (size_t)((b << 8) + s0) * OUTW_PAD - off;
            float* tb1 = tb0 + OUTW_PAD;
            #pragma unroll
            for (int q = 0; q < 4; q++) {
                int tgl = t0 + (half << 7) + tl + (q << 5);
                if (tgl >= off && tgl < Ti) {
                    float2 v = u2f(acc[mp][q]);
                    tb0[tgl] += v.x + sb0;
                    tb1[tgl] += v.y + sb1;
                }
            }
        }
    }
}

// out[b][s][t] = bias[s] + sum_k wT[k][s] * relu(in[b][k][t])   (256x256 GEMM)
// 1024 threads, 128-col tile, channel-packed f32x2.
// smem: inS [256][128] + wS [64][256] = 49152 floats
__global__ void __launch_bounds__(1024) post_kernel(
    const float* __restrict__ in, const float* __restrict__ wT,
    const float* __restrict__ bias, float* __restrict__ outp, int ostride)
{
    extern __shared__ float smem[];
    float* inS = smem;            // [256][128]
    float* wS  = smem + 32768;    // [64][256] staged per k-chunk (s contiguous)
    const int tid = threadIdx.x;
    const int b = blockIdx.y;
    const int t0 = blockIdx.x << 7;

    #pragma unroll 1
    for (int i = tid; i < 32768; i += 1024) {
        int k = i >> 7, tt = i & 127;
        int t = t0 + tt;
        float v = (t < OUTW) ? in[(size_t)((b << 8) + k) * OUTW_PAD + t] : 0.f;
        inS[i] = fmaxf(v, 0.f);
    }
    const int tl = tid & 31;
    const int wp = tid >> 5;   // 0..31
    ull acc[4][4];
    #pragma unroll
    for (int mp = 0; mp < 4; mp++) {
        int s0 = (wp << 1) + (mp << 6);
        ull bv = pack2(bias[s0], bias[s0 + 1]);
        #pragma unroll
        for (int q = 0; q < 4; q++) acc[mp][q] = bv;
    }
    #pragma unroll 1
    for (int kc = 0; kc < 4; kc++) {
        __syncthreads();
        #pragma unroll 1
        for (int i = tid; i < 16384; i += 1024) wS[i] = wT[(kc << 14) + i];
        __syncthreads();
        #pragma unroll 1
        for (int kk = 0; kk < 64; kk++) {
            const float* ir = inS + (((kc << 6) + kk) << 7) + tl;
            ull o[4];
            #pragma unroll
            for (int q = 0; q < 4; q++) o[q] = pack2(ir[q << 5]);
            const float* wr = wS + (kk << 8) + (wp << 1);
            #pragma unroll
            for (int mp = 0; mp < 4; mp++) {
                ull w = *(const ull*)(wr + (mp << 6));
                #pragma unroll
                for (int q = 0; q < 4; q++) fma2(acc[mp][q], w, o[q]);
            }
        }
    }
    #pragma unroll
    for (int mp = 0; mp < 4; mp++) {
        int s0 = (wp << 1) + (mp << 6);
        float* op0 = outp + (size_t)((b << 8) + s0) * ostride + t0;
        float* op1 = op0 + ostride;
        #pragma unroll
        for (int q = 0; q < 4; q++) {
            int tt = tl + (q << 5);
            if (t0 + tt < OUTW) {
                float2 v = u2f(acc[mp][q]);
                op0[tt] = v.x;
                op1[tt] = v.y;
            }
        }
    }
}

extern "C" void kernel_launch(void* const* d_in, const int* in_sizes, int n_in,
                              void* d_out, int out_size)
{
    const int*   x        = (const int*)d_in[0];
    const float* causal_w = (const float*)d_in[1];
    const float* causal_b = (const float*)d_in[2];
    const float* filt_w   = (const float*)d_in[3];
    const float* filt_b   = (const float*)d_in[4];
    const float* gate_w   = (const float*)d_in[5];
    const float* gate_b   = (const float*)d_in[6];
    const float* dense_w  = (const float*)d_in[7];
    const float* dense_b  = (const float*)d_in[8];
    const float* skip_w   = (const float*)d_in[9];
    const float* skip_b   = (const float*)d_in[10];
    const float* pp1_w    = (const float*)d_in[11];
    const float* pp1_b    = (const float*)d_in[12];
    const float* pp2_w    = (const float*)d_in[13];
    const float* pp2_b    = (const float*)d_in[14];
    float* out = (float*)d_out;

    float *h0, *h1, *total, *c1, *w1T, *w2T;
    cudaGetSymbolAddress((void**)&h0, g_h0);
    cudaGetSymbolAddress((void**)&h1, g_h1);
    cudaGetSymbolAddress((void**)&total, g_total);
    cudaGetSymbolAddress((void**)&c1, g_c1);
    cudaGetSymbolAddress((void**)&w1T, g_w1T);
    cudaGetSymbolAddress((void**)&w2T, g_w2T);

    static const int dil[NL] = {1, 2, 4, 8, 16, 32, 64, 128, 256, 512,
                                1, 2, 4, 8, 16, 32, 64, 128, 256, 512};

    cudaFuncSetAttribute(layer_kernel,  cudaFuncAttributeMaxDynamicSharedMemorySize, 53504 * 4);
    cudaFuncSetAttribute(causal_kernel, cudaFuncAttributeMaxDynamicSharedMemorySize, 32768 * 4);
    cudaFuncSetAttribute(post_kernel,   cudaFuncAttributeMaxDynamicSharedMemorySize, 49152 * 4);

    int nTot = NB * NS * OUTW_PAD;
    zero_kernel<<<(nTot + 255) / 256, 256>>>(total, nTot);

    dim3 cg((NT - 1 + 255) / 256, NB);
    causal_kernel<<<cg, 256, 32768 * 4>>>(x, causal_w, causal_b, h0);

    float* hc = h0;
    float* hn = h1;
    int Lh = NT - 1;
    for (int i = 0; i < NL; i++) {
        int d = dil[i];
        int Ti = Lh - d;
        int off = Ti - OUTW;
        dim3 g((Ti + TT - 1) / TT, NB);
        layer_kernel<<<g, 1024, 53504 * 4>>>(
            hc, hn,
            filt_w + (size_t)i * ND * NR * 2, filt_b + (size_t)i * ND,
            gate_w + (size_t)i * ND * NR * 2, gate_b + (size_t)i * ND,
            dense_w + (size_t)i * NR * ND,    dense_b + (size_t)i * NR,
            skip_w + (size_t)i * NS * ND,     skip_b + (size_t)i * NS,
            total, d, Lh, Ti, off);
        float* tmp = hc; hc = hn; hn = tmp;
        Lh = Ti;
    }

    transpose_kernel<<<256, 256>>>(pp1_w, w1T);
    transpose_kernel<<<256, 256>>>(pp2_w, w2T);

    dim3 pg((OUTW + 127) / 128, NB);
    post_kernel<<<pg, 1024, 49152 * 4>>>(total, w1T, pp1_b, c1, OUTW_PAD);
    post_kernel<<<pg, 1024, 49152 * 4>>>(c1, w2T, pp2_b, out, OUTW);
}

// round 5
// speedup vs baseline: 2.7669x; 1.1128x over previous
#include <cuda_runtime.h>
#include <math.h>

#define NB 8
#define NT 16384
#define NQ 256
#define NR 64
#define ND 64
#define NS 256
#define NL 20
#define OUTW 14337
#define OUTW_PAD 14368
#define TT 256
#define AS 258   // padded row stride for act

typedef unsigned long long ull;

__device__ __forceinline__ ull pack2(float x) {
    ull r; asm("mov.b64 %0, {%1, %1};" : "=l"(r) : "f"(x)); return r;
}
__device__ __forceinline__ ull pack2(float lo, float hi) {
    ull r; asm("mov.b64 %0, {%1, %2};" : "=l"(r) : "f"(lo), "f"(hi)); return r;
}
__device__ __forceinline__ void fma2(ull& d, ull a, ull b) {
    asm("fma.rn.f32x2 %0, %1, %2, %0;" : "+l"(d) : "l"(a), "l"(b));
}
__device__ __forceinline__ float2 u2f(ull v) {
    float2 f; asm("mov.b64 {%0, %1}, %2;" : "=f"(f.x), "=f"(f.y) : "l"(v)); return f;
}

// Scratch (device globals; no allocation allowed)
__device__ float g_h0[NB * NR * NT];
__device__ float g_h1[NB * NR * NT];
__device__ float g_acts[NL * NB * NR * OUTW_PAD];   // gated activations per layer (skip inputs)
__device__ float g_swT[NL * ND * NS];               // [k=li*64+dc][s]
__device__ float g_sbsum[NS];
__device__ float g_w1T[NS * NS];
__device__ float g_w2T[NQ * NS];

// wT[k][s] = w[s][k], 256x256
__global__ void transpose_kernel(const float* __restrict__ w, float* __restrict__ wT) {
    int i = blockIdx.x * 256 + threadIdx.x;
    int k = i >> 8, s = i & 255;
    wT[i] = w[(s << 8) + k];
}

// swT[k][s] = skip_w[li][s][dc], k = li*64+dc
__global__ void skipw_kernel(const float* __restrict__ sw, float* __restrict__ swT) {
    int k = blockIdx.x;          // 0..1279
    int s = threadIdx.x;         // 0..255
    int li = k >> 6, dc = k & 63;
    swT[k * NS + s] = sw[li * (NS * ND) + s * ND + dc];
}

// sbsum[s] = sum_li skip_b[li][s]
__global__ void sbsum_kernel(const float* __restrict__ sb, float* __restrict__ sbsum) {
    int s = threadIdx.x;
    float v = 0.f;
    #pragma unroll
    for (int li = 0; li < NL; li++) v += sb[li * NS + s];
    sbsum[s] = v;
}

// h[b][r][t] = cw[r][x[b,t]][0] + cw[r][x[b,t+1]][1] + cb[r]   (one-hot conv == gather)
__global__ void __launch_bounds__(256) causal_kernel(
    const int* __restrict__ x, const float* __restrict__ cw,
    const float* __restrict__ cb, float* __restrict__ h)
{
    extern __shared__ float sm[];               // 32768 floats: cw [r][q][k]
    __shared__ float cbS[64];
    for (int i = threadIdx.x; i < NR * NQ * 2; i += 256) sm[i] = cw[i];
    if (threadIdx.x < 64) cbS[threadIdx.x] = cb[threadIdx.x];
    __syncthreads();
    int b = blockIdx.y;
    int t = blockIdx.x * 256 + threadIdx.x;
    if (t >= NT - 1) return;
    int q0 = x[b * NT + t] * 2;
    int q1 = x[b * NT + t + 1] * 2 + 1;
    float* hp = h + ((size_t)b << 20) + t;
    #pragma unroll 4
    for (int r = 0; r < 64; r++) {
        hp[r << 14] = sm[(r << 9) + q0] + sm[(r << 9) + q1] + cbS[r];
    }
}

// Fused WaveNet layer (no skip), 1024 threads, 256 time cols per CTA.
// SMEM layout (floats):
//   [0, 8192)        wfT (k,r,dc)       -- dead after phase1
//   [8192, 16384)    wgT (k,r,dc)       -- dead after phase1
//   [0, 16512)       act [64][258]      -- written after phase1 (overlaps wfT/wgT)
//   [16512, 20608)   dwS [r][dc]
//   [20608, 36992)   hA  [64][256]      -- dead after phase1
//   [36992, 53376)   hB  [64][256]
// total 53376 floats = 213504 B
__global__ void __launch_bounds__(1024) layer_kernel(
    const float* __restrict__ hcur, float* __restrict__ hnext,
    const float* __restrict__ fw, const float* __restrict__ fb,
    const float* __restrict__ gw, const float* __restrict__ gb,
    const float* __restrict__ dw, const float* __restrict__ db,
    float* __restrict__ acts,
    int li, int dil, int Lh, int Ti, int off)
{
    extern __shared__ float smem[];
    float* wfT = smem;
    float* wgT = smem + 8192;
    float* act = smem;              // [64][258], valid after phase1
    float* dwS = smem + 16512;
    float* hA  = smem + 20608;
    float* hB  = smem + 36992;

    const int tid = threadIdx.x;
    const int b = blockIdx.y;
    const int t0 = blockIdx.x * TT;

    // stage weights; fw/gw transposed to (k,r,dc) so inner reads are conflict-free
    #pragma unroll 1
    for (int i = tid; i < 8192; i += 1024) {
        int dcq = i >> 7, r = (i >> 1) & 63, k = i & 1;
        int si = (k << 12) + (r << 6) + dcq;
        wfT[si] = fw[i];
        wgT[si] = gw[i];
    }
    for (int i = tid; i < 4096; i += 1024) dwS[i] = dw[i];

    const float* hbase = hcur + ((size_t)b << 20);
    #pragma unroll 1
    for (int i = tid; i < 64 * TT; i += 1024) {
        int r = i >> 8, tt = i & 255;
        int ta = t0 + tt;
        hA[i] = (ta < Lh) ? hbase[(r << 14) + ta] : 0.f;
        int tb = ta + dil;
        hB[i] = (tb < Lh) ? hbase[(r << 14) + tb] : 0.f;
    }
    __syncthreads();

    // ---- Phase 1: filter/gate GEMM (K=64, 2 taps), 16 time cols/thread ----
    const int dc = tid & 63;
    const int tg = tid >> 6;        // 0..15 : 16 time cols each
    ull facc2[8], gacc2[8];
    {
        ull fb2 = pack2(fb[dc]);
        ull gb2 = pack2(gb[dc]);
        #pragma unroll
        for (int j = 0; j < 8; j++) { facc2[j] = fb2; gacc2[j] = gb2; }
        const float* hap = hA + (tg << 4);
        const float* hbp = hB + (tg << 4);
        #pragma unroll 2
        for (int r = 0; r < 64; r++) {
            ull wf0 = pack2(wfT[(r << 6) + dc]);
            ull wf1 = pack2(wfT[4096 + (r << 6) + dc]);
            ull wg0 = pack2(wgT[(r << 6) + dc]);
            ull wg1 = pack2(wgT[4096 + (r << 6) + dc]);
            const float* ha = hap + (r << 8);
            const float* hb = hbp + (r << 8);
            #pragma unroll
            for (int j = 0; j < 4; j++) {
                ulonglong2 A = *(const ulonglong2*)(ha + (j << 2));
                ulonglong2 C = *(const ulonglong2*)(hb + (j << 2));
                fma2(facc2[2*j],   wf0, A.x);
                fma2(facc2[2*j+1], wf0, A.y);
                fma2(facc2[2*j],   wf1, C.x);
                fma2(facc2[2*j+1], wf1, C.y);
                fma2(gacc2[2*j],   wg0, A.x);
                fma2(gacc2[2*j+1], wg0, A.y);
                fma2(gacc2[2*j],   wg1, C.x);
                fma2(gacc2[2*j+1], wg1, C.y);
            }
        }
        // out = tanh(f) * sigmoid(g)
        #pragma unroll
        for (int j = 0; j < 8; j++) {
            float2 f = u2f(facc2[j]);
            float2 g = u2f(gacc2[j]);
            float ef0 = __expf(fminf(-2.f * f.x, 80.f));
            float ef1 = __expf(fminf(-2.f * f.y, 80.f));
            float eg0 = __expf(fminf(-g.x, 80.f));
            float eg1 = __expf(fminf(-g.y, 80.f));
            float o0 = __fdividef(1.f - ef0, (1.f + ef0) * (1.f + eg0));
            float o1 = __fdividef(1.f - ef1, (1.f + ef1) * (1.f + eg1));
            facc2[j] = pack2(o0, o1);
        }
    }
    __syncthreads();    // all wfT/wgT/hA reads done

    // write activation tile to smem
    {
        float* row = act + dc * AS + (tg << 4);
        #pragma unroll
        for (int j = 0; j < 8; j++)
            *(float2*)(row + (j << 1)) = u2f(facc2[j]);
    }
    __syncthreads();

    // store act tile to global (skip input), cols >= off, aligned to skip index
    {
        float* abase = acts + (size_t)((li * NB + b) * 64) * OUTW_PAD - off;
        #pragma unroll 1
        for (int i = tid; i < 64 * TT; i += 1024) {
            int dcw = i >> 8, tt = i & 255;
            int tgl = t0 + tt;
            if (tgl >= off && tgl < Ti)
                abase[(size_t)dcw * OUTW_PAD + tgl] = act[dcw * AS + tt];
        }
    }

    const int tl = tid & 31;
    const int wp = tid >> 5;   // 0..31

    // ---- Phase 2: dense 1x1 (D->R) + residual -> hnext, time-packed ----
    {
        ull acc[2][4];
        #pragma unroll
        for (int m = 0; m < 2; m++) {
            ull dbv = pack2(db[wp + (m << 5)]);
            #pragma unroll
            for (int p = 0; p < 4; p++) acc[m][p] = dbv;
        }
        #pragma unroll 1
        for (int dcc = 0; dcc < 64; dcc++) {
            const float* ar = act + dcc * AS + (tl << 1);
            ull o[4];
            #pragma unroll
            for (int p = 0; p < 4; p++) o[p] = *(const ull*)(ar + (p << 6));
            #pragma unroll
            for (int m = 0; m < 2; m++) {
                ull w = pack2(dwS[((wp + (m << 5)) << 6) + dcc]);
                #pragma unroll
                for (int p = 0; p < 4; p++) fma2(acc[m][p], w, o[p]);
            }
        }
        float* hnb = hnext + ((size_t)b << 20);
        #pragma unroll
        for (int m = 0; m < 2; m++) {
            int r = wp + (m << 5);
            #pragma unroll
            for (int p = 0; p < 4; p++) {
                int tt = (tl << 1) + (p << 6);
                int tgl = t0 + tt;
                float2 hv = *(const float2*)(hB + (r << 8) + tt);
                float2 v = u2f(acc[m][p]);
                v.x += hv.x; v.y += hv.y;
                if (tgl + 1 < Ti) {
                    *(float2*)(hnb + (r << 14) + tgl) = v;
                } else if (tgl < Ti) {
                    hnb[(r << 14) + tgl] = v.x;
                }
            }
        }
    }
}

// Fused post chain: total(K=1280 GEMM over acts) -> +sbsum,relu -> pp1(K=256)
//   -> +b1,relu -> pp2(K=256) -> +b2 -> out.   1024 threads, 128 time cols/CTA.
// smem: inS [64][128]=8192, wS [64][256]=16384, buf [256][128]=32768 -> 57344 floats
__global__ void __launch_bounds__(1024) fused_post_kernel(
    const float* __restrict__ acts, const float* __restrict__ swT,
    const float* __restrict__ sbsum,
    const float* __restrict__ w1T, const float* __restrict__ b1,
    const float* __restrict__ w2T, const float* __restrict__ b2,
    float* __restrict__ outp)
{
    extern __shared__ float smem[];
    float* inS = smem;            // [64][128]
    float* wS  = smem + 8192;     // [64][256]
    float* buf = smem + 24576;    // [256][128]
    const int tid = threadIdx.x;
    const int b = blockIdx.y;
    const int t0 = blockIdx.x << 7;
    const int tl = tid & 31;
    const int wp = tid >> 5;      // 0..31

    // ---- Stage A: skip GEMM, K = 20 layers x 64 channels ----
    ull acc[4][4];
    #pragma unroll
    for (int mp = 0; mp < 4; mp++)
        #pragma unroll
        for (int q = 0; q < 4; q++) acc[mp][q] = 0ULL;

    #pragma unroll 1
    for (int li = 0; li < NL; li++) {
        __syncthreads();
        const float* ab = acts + (size_t)((li * NB + b) * 64) * OUTW_PAD;
        #pragma unroll 1
        for (int i = tid; i < 8192; i += 1024) {
            int dcr = i >> 7, tt = i & 127;
            int t = t0 + tt;
            inS[i] = (t < OUTW) ? ab[(size_t)dcr * OUTW_PAD + t] : 0.f;
        }
        #pragma unroll 1
        for (int i = tid; i < 16384; i += 1024) wS[i] = swT[li * 16384 + i];
        __syncthreads();
        #pragma unroll 1
        for (int kk = 0; kk < 64; kk++) {
            const float* ir = inS + (kk << 7) + tl;
            ull o[4];
            #pragma unroll
            for (int q = 0; q < 4; q++) o[q] = pack2(ir[q << 5]);
            const float* wr = wS + (kk << 8) + (wp << 1);
            #pragma unroll
            for (int mp = 0; mp < 4; mp++) {
                ull w = *(const ull*)(wr + (mp << 6));
                #pragma unroll
                for (int q = 0; q < 4; q++) fma2(acc[mp][q], w, o[q]);
            }
        }
    }
    // total + biasSum, relu -> buf
    #pragma unroll
    for (int mp = 0; mp < 4; mp++) {
        int s0 = (wp << 1) + (mp << 6);
        float sb0 = sbsum[s0], sb1 = sbsum[s0 + 1];
        #pragma unroll
        for (int q = 0; q < 4; q++) {
            float2 v = u2f(acc[mp][q]);
            int tt = tl + (q << 5);
            buf[(s0 << 7) + tt]       = fmaxf(v.x + sb0, 0.f);
            buf[((s0 + 1) << 7) + tt] = fmaxf(v.y + sb1, 0.f);
        }
    }

    // ---- Stage B: pp1 (K=256) ----
    #pragma unroll
    for (int mp = 0; mp < 4; mp++) {
        int s0 = (wp << 1) + (mp << 6);
        ull bv = pack2(b1[s0], b1[s0 + 1]);
        #pragma unroll
        for (int q = 0; q < 4; q++) acc[mp][q] = bv;
    }
    #pragma unroll 1
    for (int kc = 0; kc < 4; kc++) {
        __syncthreads();
        #pragma unroll 1
        for (int i = tid; i < 16384; i += 1024) wS[i] = w1T[(kc << 14) + i];
        __syncthreads();
        #pragma unroll 1
        for (int kk = 0; kk < 64; kk++) {
            const float* ir = buf + (((kc << 6) + kk) << 7) + tl;
            ull o[4];
            #pragma unroll
            for (int q = 0; q < 4; q++) o[q] = pack2(ir[q << 5]);
            const float* wr = wS + (kk << 8) + (wp << 1);
            #pragma unroll
            for (int mp = 0; mp < 4; mp++) {
                ull w = *(const ull*)(wr + (mp << 6));
                #pragma unroll
                for (int q = 0; q < 4; q++) fma2(acc[mp][q], w, o[q]);
            }
        }
    }
    __syncthreads();   // all pp1 reads of buf done
    #pragma unroll
    for (int mp = 0; mp < 4; mp++) {
        int s0 = (wp << 1) + (mp << 6);
        #pragma unroll
        for (int q = 0; q < 4; q++) {
            float2 v = u2f(acc[mp][q]);
            int tt = tl + (q << 5);
            buf[(s0 << 7) + tt]       = fmaxf(v.x, 0.f);
            buf[((s0 + 1) << 7) + tt] = fmaxf(v.y, 0.f);
        }
    }

    // ---- Stage C: pp2 (K=256) -> global out ----
    #pragma unroll
    for (int mp = 0; mp < 4; mp++) {
        int s0 = (wp << 1) + (mp << 6);
        ull bv = pack2(b2[s0], b2[s0 + 1]);
        #pragma unroll
        for (int q = 0; q < 4; q++) acc[mp][q] = bv;
    }
    #pragma unroll 1
    for (int kc = 0; kc < 4; kc++) {
        __syncthreads();
        #pragma unroll 1
        for (int i = tid; i < 16384; i += 1024) wS[i] = w2T[(kc << 14) + i];
        __syncthreads();
        #pragma unroll 1
        for (int kk = 0; kk < 64; kk++) {
            const float* ir = buf + (((kc << 6) + kk) << 7) + tl;
            ull o[4];
            #pragma unroll
            for (int q = 0; q < 4; q++) o[q] = pack2(ir[q << 5]);
            const float* wr = wS + (kk << 8) + (wp << 1);
            #pragma unroll
            for (int mp = 0; mp < 4; mp++) {
                ull w = *(const ull*)(wr + (mp << 6));
                #pragma unroll
                for (int q = 0; q < 4; q++) fma2(acc[mp][q], w, o[q]);
            }
        }
    }
    #pragma unroll
    for (int mp = 0; mp < 4; mp++) {
        int s0 = (wp << 1) + (mp << 6);
        float* op0 = outp + (size_t)((b << 8) + s0) * OUTW + t0;
        float* op1 = op0 + OUTW;
        #pragma unroll
        for (int q = 0; q < 4; q++) {
            int tt = tl + (q << 5);
            if (t0 + tt < OUTW) {
                float2 v = u2f(acc[mp][q]);
                op0[tt] = v.x;
                op1[tt] = v.y;
            }
        }
    }
}

extern "C" void kernel_launch(void* const* d_in, const int* in_sizes, int n_in,
                              void* d_out, int out_size)
{
    const int*   x        = (const int*)d_in[0];
    const float* causal_w = (const float*)d_in[1];
    const float* causal_b = (const float*)d_in[2];
    const float* filt_w   = (const float*)d_in[3];
    const float* filt_b   = (const float*)d_in[4];
    const float* gate_w   = (const float*)d_in[5];
    const float* gate_b   = (const float*)d_in[6];
    const float* dense_w  = (const float*)d_in[7];
    const float* dense_b  = (const float*)d_in[8];
    const float* skip_w   = (const float*)d_in[9];
    const float* skip_b   = (const float*)d_in[10];
    const float* pp1_w    = (const float*)d_in[11];
    const float* pp1_b    = (const float*)d_in[12];
    const float* pp2_w    = (const float*)d_in[13];
    const float* pp2_b    = (const float*)d_in[14];
    float* out = (float*)d_out;

    float *h0, *h1, *acts, *swT, *sbsum, *w1T, *w2T;
    cudaGetSymbolAddress((void**)&h0, g_h0);
    cudaGetSymbolAddress((void**)&h1, g_h1);
    cudaGetSymbolAddress((void**)&acts, g_acts);
    cudaGetSymbolAddress((void**)&swT, g_swT);
    cudaGetSymbolAddress((void**)&sbsum, g_sbsum);
    cudaGetSymbolAddress((void**)&w1T, g_w1T);
    cudaGetSymbolAddress((void**)&w2T, g_w2T);

    static const int dil[NL] = {1, 2, 4, 8, 16, 32, 64, 128, 256, 512,
                                1, 2, 4, 8, 16, 32, 64, 128, 256, 512};

    cudaFuncSetAttribute(layer_kernel,      cudaFuncAttributeMaxDynamicSharedMemorySize, 53376 * 4);
    cudaFuncSetAttribute(causal_kernel,     cudaFuncAttributeMaxDynamicSharedMemorySize, 32768 * 4);
    cudaFuncSetAttribute(fused_post_kernel, cudaFuncAttributeMaxDynamicSharedMemorySize, 57344 * 4);

    // prep (independent of layer chain)
    transpose_kernel<<<256, 256>>>(pp1_w, w1T);
    transpose_kernel<<<256, 256>>>(pp2_w, w2T);
    skipw_kernel<<<NL * ND, 256>>>(skip_w, swT);
    sbsum_kernel<<<1, 256>>>(skip_b, sbsum);

    dim3 cg((NT - 1 + 255) / 256, NB);
    causal_kernel<<<cg, 256, 32768 * 4>>>(x, causal_w, causal_b, h0);

    float* hc = h0;
    float* hn = h1;
    int Lh = NT - 1;
    for (int i = 0; i < NL; i++) {
        int d = dil[i];
        int Ti = Lh - d;
        int off = Ti - OUTW;
        dim3 g((Ti + TT - 1) / TT, NB);
        layer_kernel<<<g, 1024, 53376 * 4>>>(
            hc, hn,
            filt_w + (size_t)i * ND * NR * 2, filt_b + (size_t)i * ND,
            gate_w + (size_t)i * ND * NR * 2, gate_b + (size_t)i * ND,
            dense_w + (size_t)i * NR * ND,    dense_b + (size_t)i * NR,
            acts, i, d, Lh, Ti, off);
        float* tmp = hc; hc = hn; hn = tmp;
        Lh = Ti;
    }

    dim3 pg((OUTW + 127) / 128, NB);
    fused_post_kernel<<<pg, 1024, 57344 * 4>>>(acts, swT, sbsum,
                                               w1T, pp1_b, w2T, pp2_b, out);
}